// round 5
// baseline (speedup 1.0000x reference)
#include <cuda_runtime.h>

#define DIMS   120
#define NPIX   14400        // 120*120
#define SS2    81
#define B64    64
#define PITCH  84           // 81 padded to 84; cols 81..83 zeroed
#define V4PIX  841          // 29*29
#define FLATN  13456        // 16*841
#define PPB    10           // pixels per v1 block (same image row)

// Intermediates (allocation-free scratch)
__device__ float g_cplx[8 * NPIX * B64];    // [s][pix][b]
__device__ float g_part[V4PIX * 128];       // [p][b*2+cls] decision partials

typedef unsigned long long ull;

__device__ __forceinline__ void fma_x2(ull& d, ull a, ull b) {
    asm("fma.rn.f32x2 %0, %1, %2, %0;" : "+l"(d) : "l"(a), "l"(b));
}
__device__ __forceinline__ float hsum_x2(ull v) {
    float2 f = *reinterpret_cast<float2*>(&v);
    return f.x + f.y;
}
__device__ __forceinline__ void cp_async4(void* smem_dst, const void* gmem_src) {
    unsigned s = (unsigned)__cvta_generic_to_shared(smem_dst);
    asm volatile("cp.async.ca.shared.global [%0], [%1], 4;" :: "r"(s), "l"(gmem_src));
}
__device__ __forceinline__ void cp_commit() {
    asm volatile("cp.async.commit_group;");
}

// ---------------------------------------------------------------------------
// V1: per-pixel 64x32x81 GEMM + relu + phase-mean. 128 threads, 1 pixel per
// iteration, 10 pixels per block. Tile 4 batches x 4 channels per thread,
// f32x2 over (k even, k odd). Weights double-buffered via cp.async (issued a
// full GEMM ahead); patches single-buffered cp.async. 45KB smem -> 5 blk/SM.
// ---------------------------------------------------------------------------
__global__ __launch_bounds__(128, 5)
void v1_kernel(const float* __restrict__ x, const float* __restrict__ w)
{
    __shared__ __align__(16) float w_s[2][32][PITCH];
    __shared__ __align__(16) float p_s[B64][PITCH];
    __shared__ __align__(16) float bounce[8 * 68];

    int t = threadIdx.x;
    int row_i = blockIdx.x / 12;            // image row
    int j0    = (blockIdx.x % 12) * 10;     // first pixel column
    int p0    = row_i * DIMS + j0;

    // zero k-padding (cols 81..83) of all 128 rows once
    {
        float* rowp = (t < 64) ? &w_s[t >> 5][t & 31][0] : &p_s[t - 64][0];
        rowp[81] = 0.f; rowp[82] = 0.f; rowp[83] = 0.f;
    }

    int lane = t & 31, wrp = t >> 5;

    // initial carry-loop state for patch staging (depends only on t)
    int b_init = (t >= SS2) ? 1 : 0;
    int k_init = t - SS2 * b_init;
    int r_init = k_init / 9;
    int q_init = k_init - 9 * r_init;

    // weight prefetch: pixel p -> buffer buf (warp-per-channel, coalesced)
    auto wpre = [&](int p, int buf) {
#pragma unroll
        for (int g = 0; g < 8; g++) {
            int c    = wrp * 8 + g;
            int rowp = (c >> 2) + ((c & 3) << 3);    // permuted row
            const float* src = w + (c * NPIX + p) * SS2 + lane;
            float* dst = &w_s[buf][rowp][lane];
            cp_async4(dst, src);
            cp_async4(dst + 32, src + 32);
            if (lane < 17) cp_async4(dst + 64, src + 64);
        }
        cp_commit();
    };

    // patch prefetch for absolute column j (carry-based, no div/mod in loop)
    auto ppre = [&](int j) {
        const float* xb = x + (row_i << 7) + j;
        int b = b_init, k = k_init, r = r_init, q = q_init;
#pragma unroll 1
        for (int it = 0; it < 40; it++) {
            cp_async4(&p_s[b][k], xb + (b << 14) + (r << 7) + q);
            k += 47;
            bool kc = (k >= SS2);
            if (kc) k -= SS2;
            b += kc ? 2 : 1;
            r += kc ? -4 : 5;
            q += 2;
            if (q >= 9) { q -= 9; r += 1; }
        }
        if (t < 64) cp_async4(&p_s[b][k], xb + (b << 14) + (r << 7) + q);
        cp_commit();
    };

    wpre(p0, 0);        // W(0)
    ppre(j0);           // P(0)

    int tx = t & 7;     // orientation (channel quad via permuted rows)
    int ty = t >> 3;    // batch sub-index 0..15

    for (int n = 0; n < PPB; n++) {
        int p   = p0 + n;
        int buf = n & 1;

        // issue next pixel's weights NOW: hidden behind this pixel's GEMM
        if (n + 1 < PPB) {
            wpre(p + 1, buf ^ 1);                  // W(n+1)
            asm volatile("cp.async.wait_group 1;");  // W(n),P(n) done
        } else {
            asm volatile("cp.async.wait_group 0;");
        }
        __syncthreads();

        // ---- GEMM: 4b x 4c per thread ----
        const float (*wb)[PITCH] = w_s[buf];
        ull acc[4][4];
#pragma unroll
        for (int bi = 0; bi < 4; bi++)
#pragma unroll
            for (int ci = 0; ci < 4; ci++) acc[bi][ci] = 0ull;

#pragma unroll 7
        for (int kq = 0; kq < 21; kq++) {
            ulonglong2 wv[4], pv[4];
#pragma unroll
            for (int ci = 0; ci < 4; ci++)
                wv[ci] = *(const ulonglong2*)&wb[tx + (ci << 3)][kq * 4];
#pragma unroll
            for (int bi = 0; bi < 4; bi++)
                pv[bi] = *(const ulonglong2*)&p_s[ty + (bi << 4)][kq * 4];
#pragma unroll
            for (int bi = 0; bi < 4; bi++)
#pragma unroll
                for (int ci = 0; ci < 4; ci++) {
                    fma_x2(acc[bi][ci], pv[bi].x, wv[ci].x);
                    fma_x2(acc[bi][ci], pv[bi].y, wv[ci].y);
                }
        }
        __syncthreads();   // all reads of w_s[buf] & p_s complete

        // patches for next pixel can start streaming in now
        if (n + 1 < PPB) ppre(j0 + n + 1);         // P(n+1)

        // ---- relu + phase-mean -> bounce (pitch 68, conflict-free) ----
#pragma unroll
        for (int bi = 0; bi < 4; bi++) {
            float s0 = fmaxf(hsum_x2(acc[bi][0]), 0.f);
            float s1 = fmaxf(hsum_x2(acc[bi][1]), 0.f);
            float s2 = fmaxf(hsum_x2(acc[bi][2]), 0.f);
            float s3 = fmaxf(hsum_x2(acc[bi][3]), 0.f);
            bounce[tx * 68 + ty + (bi << 4)] = (s0 + s1 + s2 + s3) * 0.25f;
        }
        __syncthreads();

        // ---- coalesced store: 8 orient x 64 batch ----
        {
            int s2i = t >> 4;               // orientation 0..7
            int m   = t & 15;
            float4 v = *(const float4*)&bounce[s2i * 68 + m * 4];
            *(float4*)&g_cplx[(s2i * NPIX + p) * B64 + m * 4] = v;
        }
        __syncthreads();   // bounce reads done before next pixel's bounce write
    }
}

// ---------------------------------------------------------------------------
// V4 locally-connected pooling + fused decision partials. One block per V4
// pixel. After accumulating v4[b,o], each block folds its outputs into
// per-pixel decision partials with a fixed-order smem reduction.
// ---------------------------------------------------------------------------
__global__ __launch_bounds__(128, 8)
void v4_kernel(const float* __restrict__ vw, const float* __restrict__ dw)
{
    int p  = blockIdx.x;                 // 0..840
    int ii = p / 29;
    int jj = p - ii * 29;
    int base_pix = (ii * 4) * DIMS + jj * 4;

    __shared__ __align__(16) float w_s[64][32];    // [k][o duplicated x2]
    __shared__ __align__(16) float p_s[64][64];    // [pos][b]
    __shared__ float red[8][130];                  // [to][b*2+cls], padded

    int t  = threadIdx.x;
    int to = t & 7;
    int tb = t >> 3;
    int o0 = to * 2;
    int b0 = tb * 4;

    ull acc[2][2];
    acc[0][0] = acc[0][1] = acc[1][0] = acc[1][1] = 0ull;

    for (int s = 0; s < 8; s++) {
        __syncthreads();
        for (int f = t; f < 256; f += 128) {
            int o = f >> 4, kq = f & 15;
            float4 v = *(const float4*)&vw[((((o << 3) + s) * V4PIX) + p) * 64 + kq * 4];
            *(float2*)&w_s[kq * 4 + 0][o * 2] = make_float2(v.x, v.x);
            *(float2*)&w_s[kq * 4 + 1][o * 2] = make_float2(v.y, v.y);
            *(float2*)&w_s[kq * 4 + 2][o * 2] = make_float2(v.z, v.z);
            *(float2*)&w_s[kq * 4 + 3][o * 2] = make_float2(v.w, v.w);
        }
        const float* cb = g_cplx + s * (NPIX * B64);
        for (int f = t; f < 1024; f += 128) {
            int pos = f >> 4, bq = f & 15;
            int di = pos >> 3, dj = pos & 7;
            float4 v = *(const float4*)&cb[(base_pix + di * DIMS + dj) * B64 + bq * 4];
            *(float4*)&p_s[pos][bq * 4] = v;
        }
        __syncthreads();

#pragma unroll
        for (int k = 0; k < 64; k++) {
            ulonglong2 pv = *(const ulonglong2*)&p_s[k][b0];
            ull wv0 = *(const ull*)&w_s[k][o0 * 2];
            ull wv1 = *(const ull*)&w_s[k][(o0 + 1) * 2];
            fma_x2(acc[0][0], pv.x, wv0);
            fma_x2(acc[0][1], pv.x, wv1);
            fma_x2(acc[1][0], pv.y, wv0);
            fma_x2(acc[1][1], pv.y, wv1);
        }
    }

    // ---- fused decision partials ----
    float part[4][2];
#pragma unroll
    for (int bi = 0; bi < 4; bi++) { part[bi][0] = 0.f; part[bi][1] = 0.f; }
#pragma unroll
    for (int bp = 0; bp < 2; bp++)
#pragma unroll
        for (int oi = 0; oi < 2; oi++) {
            float2 f = *reinterpret_cast<float2*>(&acc[bp][oi]);
            int o = o0 + oi;
            float w0 = dw[o * V4PIX + p];
            float w1 = dw[FLATN + o * V4PIX + p];
            part[bp * 2 + 0][0] += f.x * w0;  part[bp * 2 + 0][1] += f.x * w1;
            part[bp * 2 + 1][0] += f.y * w0;  part[bp * 2 + 1][1] += f.y * w1;
        }
    __syncthreads();   // p_s/w_s free; red region reuse is its own array
#pragma unroll
    for (int bi = 0; bi < 4; bi++) {
        red[to][(b0 + bi) * 2 + 0] = part[bi][0];
        red[to][(b0 + bi) * 2 + 1] = part[bi][1];
    }
    __syncthreads();

    // 128 threads = 64 b x 2 cls; fixed-order sum over to
    float ssum = 0.f;
#pragma unroll
    for (int u = 0; u < 8; u++) ssum += red[u][t];
    g_part[p * 128 + t] = ssum;
}

// ---------------------------------------------------------------------------
// dec2: final reduction over the 841 pixels. 1 block, 128 threads
// (thread = b*2+cls), fixed order.
// ---------------------------------------------------------------------------
__global__ __launch_bounds__(128)
void dec2_kernel(const float* __restrict__ db, float* __restrict__ out)
{
    int t = threadIdx.x;
    float ssum = 0.f;
#pragma unroll 4
    for (int p = 0; p < V4PIX; p++)
        ssum += g_part[p * 128 + t];
    out[t] = ssum + db[t & 1];
}

// ---------------------------------------------------------------------------
extern "C" void kernel_launch(void* const* d_in, const int* in_sizes, int n_in,
                              void* d_out, int out_size)
{
    const float* x  = (const float*)d_in[0];   // [64,1,128,128]
    const float* sw = (const float*)d_in[1];   // [32,120,120,81]
    const float* vw = (const float*)d_in[2];   // [16,8,29,29,64]
    const float* dw = (const float*)d_in[3];   // [2,13456]
    const float* db = (const float*)d_in[4];   // [2]
    float* out = (float*)d_out;                // [64,2]

    v1_kernel<<<NPIX / PPB, 128>>>(x, sw);
    v4_kernel<<<V4PIX, 128>>>(vw, dw);
    dec2_kernel<<<1, 128>>>(db, out);
}

// round 7
// speedup vs baseline: 1.2825x; 1.2825x over previous
#include <cuda_runtime.h>
#include <cstdint>

#define DIMS   120
#define NPIX   14400        // 120*120
#define SS2    81
#define B64    64
#define PITCH  84           // 81 padded to 84; cols 81..83 zeroed (bank-rotating pitch)
#define V4PIX  841          // 29*29
#define FLATN  13456        // 16*841
#define PPB    10           // pixels per v1 block (same image row)

// Intermediates (allocation-free scratch)
__device__ float g_cplx[8 * NPIX * B64];    // [s][pix][b]
__device__ float g_v4[B64 * FLATN];         // [b][o*841 + pix]

typedef unsigned long long ull;

__device__ __forceinline__ void fma_x2(ull& d, ull a, ull b) {
    asm("fma.rn.f32x2 %0, %1, %2, %0;" : "+l"(d) : "l"(a), "l"(b));
}
__device__ __forceinline__ float hsum_x2(ull v) {
    float2 f = *reinterpret_cast<float2*>(&v);
    return f.x + f.y;
}
__device__ __forceinline__ void cp_async4(void* smem_dst, const void* gmem_src) {
    unsigned s = (unsigned)__cvta_generic_to_shared(smem_dst);
    asm volatile("cp.async.ca.shared.global [%0], [%1], 4;" :: "r"(s), "l"(gmem_src));
}
__device__ __forceinline__ void cp_async16(void* smem_dst, const void* gmem_src) {
    unsigned s = (unsigned)__cvta_generic_to_shared(smem_dst);
    asm volatile("cp.async.cg.shared.global [%0], [%1], 16;" :: "r"(s), "l"(gmem_src));
}
__device__ __forceinline__ void cp_commit() {
    asm volatile("cp.async.commit_group;");
}

// ---------------------------------------------------------------------------
// V1: per-pixel 64x32x81 GEMM + relu + phase-mean. 128 threads, 10 pixels per
// block. Tile 4b x 4c per thread, f32x2 over (k even, k odd). Weights
// double-buffered via cp.async; patches staged with thread=k mapping so every
// cp.async has compile-time-constant src/dst strides (no address ALU).
// ---------------------------------------------------------------------------
__global__ __launch_bounds__(128, 5)
void v1_kernel(const float* __restrict__ x, const float* __restrict__ w)
{
    __shared__ __align__(16) float w_s[2][32][PITCH];
    __shared__ __align__(16) float p_s[B64][PITCH];
    __shared__ __align__(16) float bounce[8 * 68];

    int t = threadIdx.x;
    int row_i = blockIdx.x / 12;            // image row
    int j0    = (blockIdx.x % 12) * 10;     // first pixel column
    int p0    = row_i * DIMS + j0;

    // zero k-padding (cols 81..83) of all 128 rows once
    {
        float* rowp = (t < 64) ? &w_s[t >> 5][t & 31][0] : &p_s[t - 64][0];
        rowp[81] = 0.f; rowp[82] = 0.f; rowp[83] = 0.f;
    }

    int lane = t & 31, wid = t >> 5;

    // per-thread constants for patch staging (thread = k element)
    int r0 = t / 9;                  // only meaningful for t < 81
    int q0 = t - 9 * r0;

    // weight staging: pixel p -> buffer buf (warp-per-channel, coalesced,
    // constant offsets). Does NOT commit.
    auto wpre = [&](int p, int buf) {
#pragma unroll
        for (int g = 0; g < 8; g++) {
            int c    = wid * 8 + g;
            int rowp = (c >> 2) + ((c & 3) << 3);    // permuted row
            const float* src = w + (c * NPIX + p) * SS2 + lane;
            float* dst = &w_s[buf][rowp][lane];
            cp_async4(dst, src);
            cp_async4(dst + 32, src + 32);
            if (lane < 17) cp_async4(dst + 64, src + 64);
        }
    };

    // patch staging: thread t (< 81) owns k=t; iterate all 64 batches with
    // constant strides (src += 16384 floats, dst += 84 floats). No ALU.
    auto ppre = [&](int j) {
        if (wid < 3) {
            if (t < SS2) {
                const float* src = x + (row_i << 7) + j + (r0 << 7) + q0;
                float* dst = &p_s[0][t];
#pragma unroll
                for (int b = 0; b < 64; b++)
                    cp_async4(dst + b * PITCH, src + (b << 14));
            }
        }
    };

    // prologue: stage pixel 0 (weights group, then patches group)
    wpre(p0, 0);
    cp_commit();          // G: W(0)
    ppre(j0);
    cp_commit();          // G: P(0)

    int tx = t & 7;       // orientation (channel quad via permuted rows)
    int ty = t >> 3;      // batch sub-index 0..15

    for (int n = 0; n < PPB; n++) {
        int p   = p0 + n;
        int buf = n & 1;

        // issue next pixel's weights NOW (hidden behind this pixel's GEMM)
        if (n + 1 < PPB) {
            wpre(p + 1, buf ^ 1);
            cp_commit();                               // W(n+1)
            asm volatile("cp.async.wait_group 1;");    // W(n), P(n) done
        } else {
            asm volatile("cp.async.wait_group 0;");
        }
        __syncthreads();

        // ---- GEMM: 4b x 4c per thread ----
        const float (*wb)[PITCH] = w_s[buf];
        ull acc[4][4];
#pragma unroll
        for (int bi = 0; bi < 4; bi++)
#pragma unroll
            for (int ci = 0; ci < 4; ci++) acc[bi][ci] = 0ull;

#pragma unroll 7
        for (int kq = 0; kq < 21; kq++) {
            ulonglong2 wv[4], pv[4];
#pragma unroll
            for (int ci = 0; ci < 4; ci++)
                wv[ci] = *(const ulonglong2*)&wb[tx + (ci << 3)][kq * 4];
#pragma unroll
            for (int bi = 0; bi < 4; bi++)
                pv[bi] = *(const ulonglong2*)&p_s[ty + (bi << 4)][kq * 4];
#pragma unroll
            for (int bi = 0; bi < 4; bi++)
#pragma unroll
                for (int ci = 0; ci < 4; ci++) {
                    fma_x2(acc[bi][ci], pv[bi].x, wv[ci].x);
                    fma_x2(acc[bi][ci], pv[bi].y, wv[ci].y);
                }
        }
        __syncthreads();   // all reads of w_s[buf] & p_s complete

        // patches for next pixel stream in now (p_s reads are done)
        if (n + 1 < PPB) {
            ppre(j0 + n + 1);
            cp_commit();                               // P(n+1)
        }

        // ---- relu + phase-mean -> bounce (pitch 68, conflict-free) ----
#pragma unroll
        for (int bi = 0; bi < 4; bi++) {
            float s0 = fmaxf(hsum_x2(acc[bi][0]), 0.f);
            float s1 = fmaxf(hsum_x2(acc[bi][1]), 0.f);
            float s2 = fmaxf(hsum_x2(acc[bi][2]), 0.f);
            float s3 = fmaxf(hsum_x2(acc[bi][3]), 0.f);
            bounce[tx * 68 + ty + (bi << 4)] = (s0 + s1 + s2 + s3) * 0.25f;
        }
        __syncthreads();

        // ---- coalesced store: 8 orient x 64 batch ----
        {
            int s2i = t >> 4;               // orientation 0..7
            int m   = t & 15;
            float4 v = *(const float4*)&bounce[s2i * 68 + m * 4];
            *(float4*)&g_cplx[(s2i * NPIX + p) * B64 + m * 4] = v;
        }
        __syncthreads();   // bounce reads done before next pixel's bounce write
    }
}

// ---------------------------------------------------------------------------
// V4 locally-connected pooling, double-buffered. One block per V4 pixel.
// p tiles (g_cplx, L2) prefetched with 16B cp.async one s ahead; weights
// prefetched via LDG into registers during compute, STS'd post-sync.
// Dynamic smem: w[2][64][32] (16KB) + p[2][64][64] (32KB) = 48KB.
// ---------------------------------------------------------------------------
__global__ __launch_bounds__(128)
void v4_kernel(const float* __restrict__ vw)
{
    extern __shared__ __align__(16) float vsm[];
    float (*w_s)[64][32] = (float (*)[64][32])vsm;              // [2][64][32]
    float (*p_s)[64][64] = (float (*)[64][64])(vsm + 4096);     // [2][64][64]

    int p  = blockIdx.x;                 // 0..840
    int ii = p / 29;
    int jj = p - ii * 29;
    int base_pix = (ii * 4) * DIMS + jj * 4;

    int t  = threadIdx.x;
    int to = t & 7, tb = t >> 3;
    int o0 = to * 2, b0 = tb * 4;

    int wo  = t >> 4;            // weight-staging: o for first half
    int wkq = t & 15;

    auto stage_p = [&](int s, int buf) {
#pragma unroll
        for (int f0 = 0; f0 < 8; f0++) {
            int f = t + f0 * 128;
            int pos = f >> 4, bq = f & 15;
            int di = pos >> 3, dj = pos & 7;
            const float* src = g_cplx + (size_t)s * (NPIX * B64)
                             + (base_pix + di * DIMS + dj) * B64 + bq * 4;
            cp_async16(&p_s[buf][pos][bq * 4], src);
        }
    };
    auto ldg_w = [&](int s, float4* rw) {
#pragma unroll
        for (int h = 0; h < 2; h++) {
            int o = wo + h * 8;
            rw[h] = *(const float4*)&vw[((((o << 3) + s) * V4PIX) + p) * 64 + wkq * 4];
        }
    };
    auto sts_w = [&](int buf, const float4* rw) {
#pragma unroll
        for (int h = 0; h < 2; h++) {
            int o = wo + h * 8;
            *(float2*)&w_s[buf][wkq * 4 + 0][o * 2] = make_float2(rw[h].x, rw[h].x);
            *(float2*)&w_s[buf][wkq * 4 + 1][o * 2] = make_float2(rw[h].y, rw[h].y);
            *(float2*)&w_s[buf][wkq * 4 + 2][o * 2] = make_float2(rw[h].z, rw[h].z);
            *(float2*)&w_s[buf][wkq * 4 + 3][o * 2] = make_float2(rw[h].w, rw[h].w);
        }
    };

    ull acc[2][2];
    acc[0][0] = acc[0][1] = acc[1][0] = acc[1][1] = 0ull;

    // prologue: stage s=0
    float4 rw[2];
    ldg_w(0, rw);
    stage_p(0, 0);
    cp_commit();
    sts_w(0, rw);

    for (int s = 0; s < 8; s++) {
        int buf = s & 1;
        if (s < 7) {
            stage_p(s + 1, buf ^ 1);
            cp_commit();
            ldg_w(s + 1, rw);
            asm volatile("cp.async.wait_group 1;");
        } else {
            asm volatile("cp.async.wait_group 0;");
        }
        __syncthreads();    // p_s(s) + previous sts_w visible

#pragma unroll
        for (int k = 0; k < 64; k++) {
            ulonglong2 pv = *(const ulonglong2*)&p_s[buf][k][b0];
            ull wv0 = *(const ull*)&w_s[buf][k][o0 * 2];
            ull wv1 = *(const ull*)&w_s[buf][k][(o0 + 1) * 2];
            fma_x2(acc[0][0], pv.x, wv0);
            fma_x2(acc[0][1], pv.x, wv1);
            fma_x2(acc[1][0], pv.y, wv0);
            fma_x2(acc[1][1], pv.y, wv1);
        }
        __syncthreads();    // compute(s) done; safe to fill buf^1 weights
        if (s < 7) sts_w(buf ^ 1, rw);
    }

#pragma unroll
    for (int bp = 0; bp < 2; bp++)
#pragma unroll
        for (int oi = 0; oi < 2; oi++) {
            float2 f = *reinterpret_cast<float2*>(&acc[bp][oi]);
            int o = o0 + oi;
            g_v4[(b0 + bp * 2 + 0) * FLATN + o * V4PIX + p] = f.x;
            g_v4[(b0 + bp * 2 + 1) * FLATN + o * V4PIX + p] = f.y;
        }
}

// ---------------------------------------------------------------------------
// Decision readout: deterministic tree reduction per batch element.
// ---------------------------------------------------------------------------
__global__ __launch_bounds__(256)
void dec_kernel(const float* __restrict__ dw, const float* __restrict__ db,
                float* __restrict__ out)
{
    int b = blockIdx.x;
    int t = threadIdx.x;
    const float* v = g_v4 + b * FLATN;

    float a0 = 0.f, a1 = 0.f;
    for (int idx = t; idx < FLATN; idx += 256) {
        float vv = v[idx];
        a0 += vv * dw[idx];
        a1 += vv * dw[FLATN + idx];
    }

    __shared__ float s0[256], s1[256];
    s0[t] = a0; s1[t] = a1;
    __syncthreads();
    for (int off = 128; off > 0; off >>= 1) {
        if (t < off) { s0[t] += s0[t + off]; s1[t] += s1[t + off]; }
        __syncthreads();
    }
    if (t == 0) {
        out[b * 2 + 0] = s0[0] + db[0];
        out[b * 2 + 1] = s1[0] + db[1];
    }
}

// ---------------------------------------------------------------------------
extern "C" void kernel_launch(void* const* d_in, const int* in_sizes, int n_in,
                              void* d_out, int out_size)
{
    const float* x  = (const float*)d_in[0];   // [64,1,128,128]
    const float* sw = (const float*)d_in[1];   // [32,120,120,81]
    const float* vw = (const float*)d_in[2];   // [16,8,29,29,64]
    const float* dw = (const float*)d_in[3];   // [2,13456]
    const float* db = (const float*)d_in[4];   // [2]
    float* out = (float*)d_out;                // [64,2]

    cudaFuncSetAttribute(v4_kernel, cudaFuncAttributeMaxDynamicSharedMemorySize, 49152);

    v1_kernel<<<NPIX / PPB, 128>>>(x, sw);
    v4_kernel<<<V4PIX, 128, 49152>>>(vw);
    dec_kernel<<<B64, 256>>>(dw, db, out);
}

// round 8
// speedup vs baseline: 1.6787x; 1.3090x over previous
#include <cuda_runtime.h>
#include <cstdint>

#define DIMS   120
#define NPIX   14400        // 120*120
#define SS2    81
#define B64    64
#define PITCH  92           // 81 padded to 92; cols 81..91 zeroed. 92%32=28 (odd*4)
                            // -> banks 28*g+q all-distinct for fragment loads
#define V4PIX  841          // 29*29
#define FLATN  13456        // 16*841
#define PPB    10           // pixels per v1 block (same image row)

// Intermediates (allocation-free scratch)
__device__ float g_cplx[8 * NPIX * B64];    // [s][pix][b]
__device__ float g_v4[B64 * FLATN];         // [b][o*841 + pix]

typedef unsigned long long ull;

__device__ __forceinline__ void fma_x2(ull& d, ull a, ull b) {
    asm("fma.rn.f32x2 %0, %1, %2, %0;" : "+l"(d) : "l"(a), "l"(b));
}
__device__ __forceinline__ void cp_async4(void* smem_dst, const void* gmem_src) {
    unsigned s = (unsigned)__cvta_generic_to_shared(smem_dst);
    asm volatile("cp.async.ca.shared.global [%0], [%1], 4;" :: "r"(s), "l"(gmem_src));
}
__device__ __forceinline__ void cp_async16(void* smem_dst, const void* gmem_src) {
    unsigned s = (unsigned)__cvta_generic_to_shared(smem_dst);
    asm volatile("cp.async.cg.shared.global [%0], [%1], 16;" :: "r"(s), "l"(gmem_src));
}
__device__ __forceinline__ void cp_commit() {
    asm volatile("cp.async.commit_group;");
}
__device__ __forceinline__ uint32_t to_tf32(float f) {
    uint32_t r;
    asm("cvt.rna.tf32.f32 %0, %1;" : "=r"(r) : "f"(f));
    return r;
}

// ---------------------------------------------------------------------------
// V1 via mma.sync m16n8k8 tf32. Per pixel: D[64b, 32c] = A[64b, 88k] x
// B[32c, 88k]^T. Warp w owns m-tile w (batches 16w..16w+15), iterates 4
// n-tiles x 11 k-tiles. Fragments gathered with bank-perfect LDS.32.
// Weights double-buffered via cp.async; patches single-buffered.
// Epilogue: relu + phase-mean via shfl + bounce + coalesced store.
// ---------------------------------------------------------------------------
__global__ __launch_bounds__(128)
void v1_kernel(const float* __restrict__ x, const float* __restrict__ w)
{
    extern __shared__ __align__(16) float sm[];
    float (*w_s)[32][PITCH] = (float (*)[32][PITCH])sm;             // [2][32][92]
    float (*p_s)[PITCH]     = (float (*)[PITCH])(sm + 2 * 32 * PITCH); // [64][92]
    float* bounce           = sm + 2 * 32 * PITCH + 64 * PITCH;     // [8*64]

    int t = threadIdx.x;
    int lane = t & 31, wid = t >> 5;
    int g = lane >> 2;          // fragment row group 0..7
    int q = lane & 3;           // fragment k/col group 0..3

    int row_i = blockIdx.x / 12;
    int j0    = (blockIdx.x % 12) * 10;
    int p0    = row_i * DIMS + j0;

    // zero k-padding cols 81..91 for all 128 rows (2x32 w + 64 p), once
    {
        float* rowp = (t < 64) ? &w_s[t >> 5][t & 31][0] : &p_s[t - 64][0];
#pragma unroll
        for (int c = 81; c < 92; c++) rowp[c] = 0.f;
    }

    // per-thread constants for patch staging (thread = k element)
    int r0 = t / 9;
    int q0 = t - 9 * r0;

    // weight staging: pixel p -> w_s[buf][c][k], warp-per-channel, coalesced
    auto wpre = [&](int p, int buf) {
#pragma unroll
        for (int gg = 0; gg < 8; gg++) {
            int c = wid * 8 + gg;
            const float* src = w + (c * NPIX + p) * SS2 + lane;
            float* dst = &w_s[buf][c][lane];
            cp_async4(dst, src);
            cp_async4(dst + 32, src + 32);
            if (lane < 17) cp_async4(dst + 64, src + 64);
        }
    };
    // patch staging: thread t (<81) owns k=t; constant strides over batches
    auto ppre = [&](int j) {
        if (t < SS2) {
            const float* src = x + (row_i << 7) + j + (r0 << 7) + q0;
            float* dst = &p_s[0][t];
#pragma unroll
            for (int b = 0; b < 64; b++)
                cp_async4(dst + b * PITCH, src + (b << 14));
        }
    };

    wpre(p0, 0);
    cp_commit();          // W(0)
    ppre(j0);
    cp_commit();          // P(0)

    for (int n = 0; n < PPB; n++) {
        int p   = p0 + n;
        int buf = n & 1;

        if (n + 1 < PPB) {
            wpre(p + 1, buf ^ 1);
            cp_commit();                               // W(n+1) hidden behind MMA
            asm volatile("cp.async.wait_group 1;");    // W(n), P(n) done
        } else {
            asm volatile("cp.async.wait_group 0;");
        }
        __syncthreads();

        // ---- MMA: warp = m-tile, batches 16*wid .. +15 ----
        float d[4][4];     // [ntile][frag reg]
#pragma unroll
        for (int nt = 0; nt < 4; nt++)
#pragma unroll
            for (int r = 0; r < 4; r++) d[nt][r] = 0.f;

        const float (*wb)[PITCH] = w_s[buf];
        const float (*pb)[PITCH] = p_s;

#pragma unroll
        for (int kt = 0; kt < 11; kt++) {
            int k0 = kt * 8;
            // A fragment (16x8): rows 16*wid + g (+8), cols k0+q (+4)
            uint32_t a0 = to_tf32(pb[16 * wid + g][k0 + q]);
            uint32_t a1 = to_tf32(pb[16 * wid + g + 8][k0 + q]);
            uint32_t a2 = to_tf32(pb[16 * wid + g][k0 + q + 4]);
            uint32_t a3 = to_tf32(pb[16 * wid + g + 8][k0 + q + 4]);
#pragma unroll
            for (int nt = 0; nt < 4; nt++) {
                // B fragment (8k x 8c, col-major): col = 8*nt + g, k = k0+q (+4)
                uint32_t b0 = to_tf32(wb[8 * nt + g][k0 + q]);
                uint32_t b1 = to_tf32(wb[8 * nt + g][k0 + q + 4]);
                asm volatile(
                    "mma.sync.aligned.m16n8k8.row.col.f32.tf32.tf32.f32 "
                    "{%0,%1,%2,%3}, {%4,%5,%6,%7}, {%8,%9}, {%0,%1,%2,%3};"
                    : "+f"(d[nt][0]), "+f"(d[nt][1]), "+f"(d[nt][2]), "+f"(d[nt][3])
                    : "r"(a0), "r"(a1), "r"(a2), "r"(a3), "r"(b0), "r"(b1));
            }
        }
        __syncthreads();   // all reads of w_s[buf] & p_s complete

        // patches for next pixel stream in now
        if (n + 1 < PPB) {
            ppre(j0 + n + 1);
            cp_commit();                               // P(n+1)
        }

        // ---- relu + phase-mean ----
        // d[nt][0/1]: (b = 16w+g,   c = 8nt + 2q + {0,1})
        // d[nt][2/3]: (b = 16w+g+8, c = 8nt + 2q + {0,1})
        // orientation s = 2nt + (q>>1); lane^1 holds the other phase pair.
#pragma unroll
        for (int nt = 0; nt < 4; nt++) {
            float r01 = fmaxf(d[nt][0], 0.f) + fmaxf(d[nt][1], 0.f);
            float r23 = fmaxf(d[nt][2], 0.f) + fmaxf(d[nt][3], 0.f);
            r01 += __shfl_xor_sync(0xFFFFFFFFu, r01, 1);
            r23 += __shfl_xor_sync(0xFFFFFFFFu, r23, 1);
            if ((lane & 1) == 0) {
                int s = 2 * nt + (q >> 1);
                int b = 16 * wid + g;
                bounce[s * 64 + b]     = r01 * 0.25f;
                bounce[s * 64 + b + 8] = r23 * 0.25f;
            }
        }
        __syncthreads();

        // ---- coalesced store: 8 orient x 64 batch ----
        {
            int s2i = t >> 4;               // orientation 0..7
            int m   = t & 15;
            float4 v = *(const float4*)&bounce[s2i * 64 + m * 4];
            *(float4*)&g_cplx[(s2i * NPIX + p) * B64 + m * 4] = v;
        }
        __syncthreads();   // bounce reads done before next pixel's writes
    }
}

#define V1_SMEM ((2 * 32 * PITCH + 64 * PITCH + 8 * 64) * 4)

// ---------------------------------------------------------------------------
// V4 locally-connected pooling, double-buffered (R7, known-good).
// ---------------------------------------------------------------------------
__global__ __launch_bounds__(128)
void v4_kernel(const float* __restrict__ vw)
{
    extern __shared__ __align__(16) float vsm[];
    float (*w_s)[64][32] = (float (*)[64][32])vsm;              // [2][64][32]
    float (*p_s)[64][64] = (float (*)[64][64])(vsm + 4096);     // [2][64][64]

    int p  = blockIdx.x;
    int ii = p / 29;
    int jj = p - ii * 29;
    int base_pix = (ii * 4) * DIMS + jj * 4;

    int t  = threadIdx.x;
    int to = t & 7, tb = t >> 3;
    int o0 = to * 2, b0 = tb * 4;

    int wo  = t >> 4;
    int wkq = t & 15;

    auto stage_p = [&](int s, int buf) {
#pragma unroll
        for (int f0 = 0; f0 < 8; f0++) {
            int f = t + f0 * 128;
            int pos = f >> 4, bq = f & 15;
            int di = pos >> 3, dj = pos & 7;
            const float* src = g_cplx + (size_t)s * (NPIX * B64)
                             + (base_pix + di * DIMS + dj) * B64 + bq * 4;
            cp_async16(&p_s[buf][pos][bq * 4], src);
        }
    };
    auto ldg_w = [&](int s, float4* rw) {
#pragma unroll
        for (int h = 0; h < 2; h++) {
            int o = wo + h * 8;
            rw[h] = *(const float4*)&vw[((((o << 3) + s) * V4PIX) + p) * 64 + wkq * 4];
        }
    };
    auto sts_w = [&](int buf, const float4* rw) {
#pragma unroll
        for (int h = 0; h < 2; h++) {
            int o = wo + h * 8;
            *(float2*)&w_s[buf][wkq * 4 + 0][o * 2] = make_float2(rw[h].x, rw[h].x);
            *(float2*)&w_s[buf][wkq * 4 + 1][o * 2] = make_float2(rw[h].y, rw[h].y);
            *(float2*)&w_s[buf][wkq * 4 + 2][o * 2] = make_float2(rw[h].z, rw[h].z);
            *(float2*)&w_s[buf][wkq * 4 + 3][o * 2] = make_float2(rw[h].w, rw[h].w);
        }
    };

    ull acc[2][2];
    acc[0][0] = acc[0][1] = acc[1][0] = acc[1][1] = 0ull;

    float4 rw[2];
    ldg_w(0, rw);
    stage_p(0, 0);
    cp_commit();
    sts_w(0, rw);

    for (int s = 0; s < 8; s++) {
        int buf = s & 1;
        if (s < 7) {
            stage_p(s + 1, buf ^ 1);
            cp_commit();
            ldg_w(s + 1, rw);
            asm volatile("cp.async.wait_group 1;");
        } else {
            asm volatile("cp.async.wait_group 0;");
        }
        __syncthreads();

#pragma unroll
        for (int k = 0; k < 64; k++) {
            ulonglong2 pv = *(const ulonglong2*)&p_s[buf][k][b0];
            ull wv0 = *(const ull*)&w_s[buf][k][o0 * 2];
            ull wv1 = *(const ull*)&w_s[buf][k][(o0 + 1) * 2];
            fma_x2(acc[0][0], pv.x, wv0);
            fma_x2(acc[0][1], pv.x, wv1);
            fma_x2(acc[1][0], pv.y, wv0);
            fma_x2(acc[1][1], pv.y, wv1);
        }
        __syncthreads();
        if (s < 7) sts_w(buf ^ 1, rw);
    }

#pragma unroll
    for (int bp = 0; bp < 2; bp++)
#pragma unroll
        for (int oi = 0; oi < 2; oi++) {
            float2 f = *reinterpret_cast<float2*>(&acc[bp][oi]);
            int o = o0 + oi;
            g_v4[(b0 + bp * 2 + 0) * FLATN + o * V4PIX + p] = f.x;
            g_v4[(b0 + bp * 2 + 1) * FLATN + o * V4PIX + p] = f.y;
        }
}

// ---------------------------------------------------------------------------
// Decision readout (known-good).
// ---------------------------------------------------------------------------
__global__ __launch_bounds__(256)
void dec_kernel(const float* __restrict__ dw, const float* __restrict__ db,
                float* __restrict__ out)
{
    int b = blockIdx.x;
    int t = threadIdx.x;
    const float* v = g_v4 + b * FLATN;

    float a0 = 0.f, a1 = 0.f;
    for (int idx = t; idx < FLATN; idx += 256) {
        float vv = v[idx];
        a0 += vv * dw[idx];
        a1 += vv * dw[FLATN + idx];
    }

    __shared__ float s0[256], s1[256];
    s0[t] = a0; s1[t] = a1;
    __syncthreads();
    for (int off = 128; off > 0; off >>= 1) {
        if (t < off) { s0[t] += s0[t + off]; s1[t] += s1[t + off]; }
        __syncthreads();
    }
    if (t == 0) {
        out[b * 2 + 0] = s0[0] + db[0];
        out[b * 2 + 1] = s1[0] + db[1];
    }
}

// ---------------------------------------------------------------------------
extern "C" void kernel_launch(void* const* d_in, const int* in_sizes, int n_in,
                              void* d_out, int out_size)
{
    const float* x  = (const float*)d_in[0];   // [64,1,128,128]
    const float* sw = (const float*)d_in[1];   // [32,120,120,81]
    const float* vw = (const float*)d_in[2];   // [16,8,29,29,64]
    const float* dw = (const float*)d_in[3];   // [2,13456]
    const float* db = (const float*)d_in[4];   // [2]
    float* out = (float*)d_out;                // [64,2]

    cudaFuncSetAttribute(v1_kernel, cudaFuncAttributeMaxDynamicSharedMemorySize, V1_SMEM);
    cudaFuncSetAttribute(v4_kernel, cudaFuncAttributeMaxDynamicSharedMemorySize, 49152);

    v1_kernel<<<NPIX / PPB, 128, V1_SMEM>>>(x, sw);
    v4_kernel<<<V4PIX, 128, 49152>>>(vw);
    dec_kernel<<<B64, 256>>>(dw, db, out);
}

// round 10
// speedup vs baseline: 1.9152x; 1.1409x over previous
#include <cuda_runtime.h>
#include <cstdint>

#define DIMS   120
#define NPIX   14400        // 120*120
#define SS2    81
#define B64    64
#define PITCH  92           // v1: 81 padded to 92; banks 28g+q all-distinct
#define V4PIX  841          // 29*29
#define FLATN  13456        // 16*841
#define PPB    10           // pixels per v1 block (same image row)

// Intermediates (allocation-free scratch)
__device__ float g_cplx[8 * NPIX * B64];    // [s][pix][b]
__device__ float g_part[V4PIX * 128];       // [p][b*2+cls] decision partials

__device__ __forceinline__ void cp_async4(void* smem_dst, const void* gmem_src) {
    unsigned s = (unsigned)__cvta_generic_to_shared(smem_dst);
    asm volatile("cp.async.ca.shared.global [%0], [%1], 4;" :: "r"(s), "l"(gmem_src));
}
__device__ __forceinline__ void cp_async16(void* smem_dst, const void* gmem_src) {
    unsigned s = (unsigned)__cvta_generic_to_shared(smem_dst);
    asm volatile("cp.async.cg.shared.global [%0], [%1], 16;" :: "r"(s), "l"(gmem_src));
}
__device__ __forceinline__ void cp_commit() {
    asm volatile("cp.async.commit_group;");
}
__device__ __forceinline__ uint32_t to_tf32(float f) {
    uint32_t r;
    asm("cvt.rna.tf32.f32 %0, %1;" : "=r"(r) : "f"(f));
    return r;
}

// ---------------------------------------------------------------------------
// V1 via mma.sync m16n8k8 tf32 (R8, known-good, 118us).
// ---------------------------------------------------------------------------
__global__ __launch_bounds__(128)
void v1_kernel(const float* __restrict__ x, const float* __restrict__ w)
{
    extern __shared__ __align__(16) float sm[];
    float (*w_s)[32][PITCH] = (float (*)[32][PITCH])sm;                // [2][32][92]
    float (*p_s)[PITCH]     = (float (*)[PITCH])(sm + 2 * 32 * PITCH); // [64][92]
    float* bounce           = sm + 2 * 32 * PITCH + 64 * PITCH;       // [8*64]

    int t = threadIdx.x;
    int lane = t & 31, wid = t >> 5;
    int g = lane >> 2;
    int q = lane & 3;

    int row_i = blockIdx.x / 12;
    int j0    = (blockIdx.x % 12) * 10;
    int p0    = row_i * DIMS + j0;

    {
        float* rowp = (t < 64) ? &w_s[t >> 5][t & 31][0] : &p_s[t - 64][0];
#pragma unroll
        for (int c = 81; c < 92; c++) rowp[c] = 0.f;
    }

    int r0 = t / 9;
    int q0 = t - 9 * r0;

    auto wpre = [&](int p, int buf) {
#pragma unroll
        for (int gg = 0; gg < 8; gg++) {
            int c = wid * 8 + gg;
            const float* src = w + (c * NPIX + p) * SS2 + lane;
            float* dst = &w_s[buf][c][lane];
            cp_async4(dst, src);
            cp_async4(dst + 32, src + 32);
            if (lane < 17) cp_async4(dst + 64, src + 64);
        }
    };
    auto ppre = [&](int j) {
        if (t < SS2) {
            const float* src = x + (row_i << 7) + j + (r0 << 7) + q0;
            float* dst = &p_s[0][t];
#pragma unroll
            for (int b = 0; b < 64; b++)
                cp_async4(dst + b * PITCH, src + (b << 14));
        }
    };

    wpre(p0, 0);
    cp_commit();
    ppre(j0);
    cp_commit();

    for (int n = 0; n < PPB; n++) {
        int p   = p0 + n;
        int buf = n & 1;

        if (n + 1 < PPB) {
            wpre(p + 1, buf ^ 1);
            cp_commit();
            asm volatile("cp.async.wait_group 1;");
        } else {
            asm volatile("cp.async.wait_group 0;");
        }
        __syncthreads();

        float d[4][4];
#pragma unroll
        for (int nt = 0; nt < 4; nt++)
#pragma unroll
            for (int r = 0; r < 4; r++) d[nt][r] = 0.f;

        const float (*wb)[PITCH] = w_s[buf];
        const float (*pb)[PITCH] = p_s;

#pragma unroll
        for (int kt = 0; kt < 11; kt++) {
            int k0 = kt * 8;
            uint32_t a0 = to_tf32(pb[16 * wid + g][k0 + q]);
            uint32_t a1 = to_tf32(pb[16 * wid + g + 8][k0 + q]);
            uint32_t a2 = to_tf32(pb[16 * wid + g][k0 + q + 4]);
            uint32_t a3 = to_tf32(pb[16 * wid + g + 8][k0 + q + 4]);
#pragma unroll
            for (int nt = 0; nt < 4; nt++) {
                uint32_t b0 = to_tf32(wb[8 * nt + g][k0 + q]);
                uint32_t b1 = to_tf32(wb[8 * nt + g][k0 + q + 4]);
                asm volatile(
                    "mma.sync.aligned.m16n8k8.row.col.f32.tf32.tf32.f32 "
                    "{%0,%1,%2,%3}, {%4,%5,%6,%7}, {%8,%9}, {%0,%1,%2,%3};"
                    : "+f"(d[nt][0]), "+f"(d[nt][1]), "+f"(d[nt][2]), "+f"(d[nt][3])
                    : "r"(a0), "r"(a1), "r"(a2), "r"(a3), "r"(b0), "r"(b1));
            }
        }
        __syncthreads();

        if (n + 1 < PPB) {
            ppre(j0 + n + 1);
            cp_commit();
        }

#pragma unroll
        for (int nt = 0; nt < 4; nt++) {
            float r01 = fmaxf(d[nt][0], 0.f) + fmaxf(d[nt][1], 0.f);
            float r23 = fmaxf(d[nt][2], 0.f) + fmaxf(d[nt][3], 0.f);
            r01 += __shfl_xor_sync(0xFFFFFFFFu, r01, 1);
            r23 += __shfl_xor_sync(0xFFFFFFFFu, r23, 1);
            if ((lane & 1) == 0) {
                int s = 2 * nt + (q >> 1);
                int b = 16 * wid + g;
                bounce[s * 64 + b]     = r01 * 0.25f;
                bounce[s * 64 + b + 8] = r23 * 0.25f;
            }
        }
        __syncthreads();

        {
            int s2i = t >> 4;
            int m   = t & 15;
            float4 v = *(const float4*)&bounce[s2i * 64 + m * 4];
            *(float4*)&g_cplx[(s2i * NPIX + p) * B64 + m * 4] = v;
        }
        __syncthreads();
    }
}

#define V1_SMEM ((2 * 32 * PITCH + 64 * PITCH + 8 * 64) * 4)

// ---------------------------------------------------------------------------
// V4 via mma.sync m16n8k8 tf32 + fused decision fold.
// Per pixel: D[16 o, 64 b] = W[16 o, 512 k] x P[512 k, 64 b]; fragments
// accumulate across the 8 s-tiles. Warp w owns n-tiles {2w, 2w+1}.
// FIX vs R9: stage_w now stages the FULL 64-float weight row per o
// (4 x cp.async16 per thread instead of 1 -> previously 3/4 of the tile
// was stale smem, rel_err 42).
// ---------------------------------------------------------------------------
__global__ __launch_bounds__(128)
void v4_kernel(const float* __restrict__ vw, const float* __restrict__ dw)
{
    extern __shared__ __align__(16) float vsm[];
    float* wt   = vsm;            // [2][16][68]
    float* ps   = vsm + 2176;     // [2][64][72]
    float* dwv  = vsm + 11392;    // [2][16]
    float* part = vsm + 11424;    // [128]

    int p  = blockIdx.x;
    int ii = p / 29;
    int jj = p - ii * 29;
    int base_pix = (ii * 4) * DIMS + jj * 4;

    int t = threadIdx.x;
    int lane = t & 31, wid = t >> 5;
    int g = lane >> 2;
    int q = lane & 3;

    // preload decision weights for this pixel: dwv[cls*16 + o]
    if (t < 32)
        dwv[t] = dw[(t >> 4) * FLATN + (t & 15) * V4PIX + p];

    // stage weight tile [16 o][64 k]: thread t<64 owns o=t>>2, floats
    // c4*16 .. c4*16+15 (four 16B copies).
    auto stage_w = [&](int s, int buf) {
        if (t < 64) {
            int o = t >> 2, c4 = t & 3;
            const float* src = vw + (((o << 3) + s) * V4PIX + p) * 64 + c4 * 16;
            float* dst = &wt[buf * 1088 + o * 68 + c4 * 16];
#pragma unroll
            for (int j = 0; j < 4; j++)
                cp_async16(dst + j * 4, src + j * 4);
        }
    };
    // stage patch tile [64 pos][64 b] -> pitch 72 (banks 8q+g perfect)
    auto stage_p = [&](int s, int buf) {
#pragma unroll
        for (int f0 = 0; f0 < 8; f0++) {
            int f = t + f0 * 128;
            int pos = f >> 4, bq = f & 15;
            int di = pos >> 3, dj = pos & 7;
            const float* src = g_cplx + (size_t)s * (NPIX * B64)
                             + (base_pix + di * DIMS + dj) * B64 + bq * 4;
            cp_async16(&ps[buf * 4608 + pos * 72 + bq * 4], src);
        }
    };

    float d[2][4];     // [ntile-local][frag], accumulated over all s
#pragma unroll
    for (int n = 0; n < 2; n++)
#pragma unroll
        for (int r = 0; r < 4; r++) d[n][r] = 0.f;

    stage_w(0, 0);
    stage_p(0, 0);
    cp_commit();

    for (int s = 0; s < 8; s++) {
        int buf = s & 1;
        if (s < 7) {
            stage_w(s + 1, buf ^ 1);
            stage_p(s + 1, buf ^ 1);
            cp_commit();
            asm volatile("cp.async.wait_group 1;");
        } else {
            asm volatile("cp.async.wait_group 0;");
        }
        __syncthreads();

        const float* wb = &wt[buf * 1088];
        const float* pb = &ps[buf * 4608];

#pragma unroll
        for (int kt = 0; kt < 8; kt++) {
            int k0 = kt * 8;
            uint32_t a0 = to_tf32(wb[g * 68 + k0 + q]);
            uint32_t a1 = to_tf32(wb[(g + 8) * 68 + k0 + q]);
            uint32_t a2 = to_tf32(wb[g * 68 + k0 + q + 4]);
            uint32_t a3 = to_tf32(wb[(g + 8) * 68 + k0 + q + 4]);
#pragma unroll
            for (int nl = 0; nl < 2; nl++) {
                int nt = 2 * wid + nl;
                uint32_t b0 = to_tf32(pb[(k0 + q) * 72 + 8 * nt + g]);
                uint32_t b1 = to_tf32(pb[(k0 + q + 4) * 72 + 8 * nt + g]);
                asm volatile(
                    "mma.sync.aligned.m16n8k8.row.col.f32.tf32.tf32.f32 "
                    "{%0,%1,%2,%3}, {%4,%5,%6,%7}, {%8,%9}, {%0,%1,%2,%3};"
                    : "+f"(d[nl][0]), "+f"(d[nl][1]), "+f"(d[nl][2]), "+f"(d[nl][3])
                    : "r"(a0), "r"(a1), "r"(a2), "r"(a3), "r"(b0), "r"(b1));
            }
        }
        __syncthreads();   // compute(s) done before s+2 staging overwrites buf
    }

    // ---- fused decision fold ----
    // d[nl][0/1]: (o = g,   b = 8nt + 2q + {0,1})
    // d[nl][2/3]: (o = g+8, b = 8nt + 2q + {0,1})
    float dw0g = dwv[g],      dw0h = dwv[g + 8];
    float dw1g = dwv[16 + g], dw1h = dwv[16 + g + 8];
#pragma unroll
    for (int nl = 0; nl < 2; nl++) {
        int nt = 2 * wid + nl;
        float c00 = d[nl][0] * dw0g + d[nl][2] * dw0h;   // cls0, b even
        float c01 = d[nl][1] * dw0g + d[nl][3] * dw0h;   // cls0, b odd
        float c10 = d[nl][0] * dw1g + d[nl][2] * dw1h;   // cls1, b even
        float c11 = d[nl][1] * dw1g + d[nl][3] * dw1h;   // cls1, b odd
#pragma unroll
        for (int m = 4; m < 32; m <<= 1) {
            c00 += __shfl_xor_sync(0xFFFFFFFFu, c00, m);
            c01 += __shfl_xor_sync(0xFFFFFFFFu, c01, m);
            c10 += __shfl_xor_sync(0xFFFFFFFFu, c10, m);
            c11 += __shfl_xor_sync(0xFFFFFFFFu, c11, m);
        }
        if (g == 0) {
            int b = 8 * nt + 2 * q;
            part[b * 2 + 0]       = c00;
            part[(b + 1) * 2 + 0] = c01;
            part[b * 2 + 1]       = c10;
            part[(b + 1) * 2 + 1] = c11;
        }
    }
    __syncthreads();
    g_part[p * 128 + t] = part[t];
}
#define V4_SMEM (11552 * 4)

// ---------------------------------------------------------------------------
// dec2: deterministic fixed-order sum of per-pixel partials.
// ---------------------------------------------------------------------------
__global__ __launch_bounds__(128)
void dec2_kernel(const float* __restrict__ db, float* __restrict__ out)
{
    int t = threadIdx.x;
    float ssum = 0.f;
#pragma unroll 8
    for (int p = 0; p < V4PIX; p++)
        ssum += g_part[p * 128 + t];
    out[t] = ssum + db[t & 1];
}

// ---------------------------------------------------------------------------
extern "C" void kernel_launch(void* const* d_in, const int* in_sizes, int n_in,
                              void* d_out, int out_size)
{
    const float* x  = (const float*)d_in[0];   // [64,1,128,128]
    const float* sw = (const float*)d_in[1];   // [32,120,120,81]
    const float* vw = (const float*)d_in[2];   // [16,8,29,29,64]
    const float* dw = (const float*)d_in[3];   // [2,13456]
    const float* db = (const float*)d_in[4];   // [2]
    float* out = (float*)d_out;                // [64,2]

    cudaFuncSetAttribute(v1_kernel, cudaFuncAttributeMaxDynamicSharedMemorySize, V1_SMEM);
    cudaFuncSetAttribute(v4_kernel, cudaFuncAttributeMaxDynamicSharedMemorySize, V4_SMEM);

    v1_kernel<<<NPIX / PPB, 128, V1_SMEM>>>(x, sw);
    v4_kernel<<<V4PIX, 128, V4_SMEM>>>(vw, dw);
    dec2_kernel<<<1, 128>>>(db, out);
}

// round 11
// speedup vs baseline: 2.0187x; 1.0540x over previous
#include <cuda_runtime.h>
#include <cstdint>

#define DIMS   120
#define NPIX   14400        // 120*120
#define SS2    81
#define B64    64
#define PITCH  92           // banks 28g+q (scalar) / 28g+2q (paired) conflict-free
#define V4PIX  841          // 29*29
#define FLATN  13456        // 16*841
#define PPB    10           // pixels per v1 block (same image row)

// Intermediates (allocation-free scratch)
__device__ float g_cplx[8 * NPIX * B64];    // [s][pix][b]
__device__ float g_part[V4PIX * 128];       // [p][b*2+cls] decision partials

__device__ __forceinline__ void cp_async4(void* smem_dst, const void* gmem_src) {
    unsigned s = (unsigned)__cvta_generic_to_shared(smem_dst);
    asm volatile("cp.async.ca.shared.global [%0], [%1], 4;" :: "r"(s), "l"(gmem_src));
}
__device__ __forceinline__ void cp_async16(void* smem_dst, const void* gmem_src) {
    unsigned s = (unsigned)__cvta_generic_to_shared(smem_dst);
    asm volatile("cp.async.cg.shared.global [%0], [%1], 16;" :: "r"(s), "l"(gmem_src));
}
__device__ __forceinline__ void cp_commit() {
    asm volatile("cp.async.commit_group;");
}
__device__ __forceinline__ uint32_t to_tf32(float f) {
    uint32_t r;
    asm("cvt.rna.tf32.f32 %0, %1;" : "=r"(r) : "f"(f));
    return r;
}
// interleaved k layout within each 8-col group: [0,4,1,5,2,6,3,7]
// -> logical (k0+q, k0+q+4) sit at adjacent phys cols (k0+2q, k0+2q+1)
__device__ __forceinline__ int physcol(int k) {
    return ((k >> 3) << 3) + ((k & 3) << 1) + ((k >> 2) & 1);
}

// ---------------------------------------------------------------------------
// V1 via mma.sync m16n8k8 tf32. Paired LDS.64 fragment loads (interleaved k),
// 4-warp-balanced patch staging, cp.async double-buffered weights.
// ---------------------------------------------------------------------------
__global__ __launch_bounds__(128)
void v1_kernel(const float* __restrict__ x, const float* __restrict__ w)
{
    extern __shared__ __align__(16) float sm[];
    float (*w_s)[32][PITCH] = (float (*)[32][PITCH])sm;                // [2][32][92]
    float (*p_s)[PITCH]     = (float (*)[PITCH])(sm + 2 * 32 * PITCH); // [64][92]
    float* bounce           = sm + 2 * 32 * PITCH + 64 * PITCH;       // [8*64]

    int t = threadIdx.x;
    int lane = t & 31, wid = t >> 5;
    int g = lane >> 2;
    int q = lane & 3;

    int row_i = blockIdx.x / 12;
    int j0    = (blockIdx.x % 12) * 10;
    int p0    = row_i * DIMS + j0;

    // zero phys cols 81..91 (covers all logical-pad positions k=81..87) once
    {
        float* rowp = (t < 64) ? &w_s[t >> 5][t & 31][0] : &p_s[t - 64][0];
#pragma unroll
        for (int c = 81; c < 92; c++) rowp[c] = 0.f;
    }

    // precomputed per-lane staging constants (3 k-chunks: lane, +32, +64)
    int pcol[3], rr[3], qq[3];
#pragma unroll
    for (int c = 0; c < 3; c++) {
        int k = lane + 32 * c;
        pcol[c] = physcol(k);          // valid for k < 88
        rr[c] = k / 9;
        qq[c] = k - 9 * rr[c];
    }

    // weight staging: pixel p -> w_s[buf][c][phys(k)], warp-per-channel
    auto wpre = [&](int p, int buf) {
#pragma unroll
        for (int gg = 0; gg < 8; gg++) {
            int c = wid * 8 + gg;
            const float* src = w + (c * NPIX + p) * SS2 + lane;
            float* row = &w_s[buf][c][0];
            cp_async4(row + pcol[0], src);
            cp_async4(row + pcol[1], src + 32);
            if (lane < 17) cp_async4(row + pcol[2], src + 64);
        }
    };
    // patch staging: warp w owns batches [16w, 16w+16); lane owns k-chunks
    auto ppre = [&](int j) {
        const float* xw = x + (row_i << 7) + j + (wid << 4 << 14); // +16*wid batches
        float* pw = &p_s[wid << 4][0];
#pragma unroll
        for (int c = 0; c < 3; c++) {
            if (c < 2 || lane < 17) {
                const float* src = xw + (rr[c] << 7) + qq[c];
                float* dst = pw + pcol[c];
#pragma unroll
                for (int b = 0; b < 16; b++)
                    cp_async4(dst + b * PITCH, src + (b << 14));
            }
        }
    };

    wpre(p0, 0);
    cp_commit();
    ppre(j0);
    cp_commit();

    for (int n = 0; n < PPB; n++) {
        int p   = p0 + n;
        int buf = n & 1;

        if (n + 1 < PPB) {
            wpre(p + 1, buf ^ 1);
            cp_commit();
            asm volatile("cp.async.wait_group 1;");
        } else {
            asm volatile("cp.async.wait_group 0;");
        }
        __syncthreads();

        float d[4][4];
#pragma unroll
        for (int nt = 0; nt < 4; nt++)
#pragma unroll
            for (int r = 0; r < 4; r++) d[nt][r] = 0.f;

        const float (*wb)[PITCH] = w_s[buf];
        const float (*pb)[PITCH] = p_s;

#pragma unroll
        for (int kt = 0; kt < 11; kt++) {
            int kc = kt * 8 + 2 * q;
            float2 alo = *(const float2*)&pb[16 * wid + g][kc];
            float2 ahi = *(const float2*)&pb[16 * wid + g + 8][kc];
            uint32_t a0 = to_tf32(alo.x);
            uint32_t a1 = to_tf32(ahi.x);
            uint32_t a2 = to_tf32(alo.y);
            uint32_t a3 = to_tf32(ahi.y);
#pragma unroll
            for (int nt = 0; nt < 4; nt++) {
                float2 bv = *(const float2*)&wb[8 * nt + g][kc];
                uint32_t b0 = to_tf32(bv.x);
                uint32_t b1 = to_tf32(bv.y);
                asm volatile(
                    "mma.sync.aligned.m16n8k8.row.col.f32.tf32.tf32.f32 "
                    "{%0,%1,%2,%3}, {%4,%5,%6,%7}, {%8,%9}, {%0,%1,%2,%3};"
                    : "+f"(d[nt][0]), "+f"(d[nt][1]), "+f"(d[nt][2]), "+f"(d[nt][3])
                    : "r"(a0), "r"(a1), "r"(a2), "r"(a3), "r"(b0), "r"(b1));
            }
        }
        __syncthreads();

        if (n + 1 < PPB) {
            ppre(j0 + n + 1);
            cp_commit();
        }

        // relu + phase-mean (c = 8nt + 2q + {0,1}; phases = c&3)
#pragma unroll
        for (int nt = 0; nt < 4; nt++) {
            float r01 = fmaxf(d[nt][0], 0.f) + fmaxf(d[nt][1], 0.f);
            float r23 = fmaxf(d[nt][2], 0.f) + fmaxf(d[nt][3], 0.f);
            r01 += __shfl_xor_sync(0xFFFFFFFFu, r01, 1);
            r23 += __shfl_xor_sync(0xFFFFFFFFu, r23, 1);
            if ((lane & 1) == 0) {
                int s = 2 * nt + (q >> 1);
                int b = 16 * wid + g;
                bounce[s * 64 + b]     = r01 * 0.25f;
                bounce[s * 64 + b + 8] = r23 * 0.25f;
            }
        }
        __syncthreads();

        {
            int s2i = t >> 4;
            int m   = t & 15;
            float4 v = *(const float4*)&bounce[s2i * 64 + m * 4];
            *(float4*)&g_cplx[(s2i * NPIX + p) * B64 + m * 4] = v;
        }
        __syncthreads();
    }
}

#define V1_SMEM ((2 * 32 * PITCH + 64 * PITCH + 8 * 64) * 4)

// ---------------------------------------------------------------------------
// V4 via mma.sync m16n8k8 tf32 + fused decision fold (R10, known-good).
// ---------------------------------------------------------------------------
__global__ __launch_bounds__(128)
void v4_kernel(const float* __restrict__ vw, const float* __restrict__ dw)
{
    extern __shared__ __align__(16) float vsm[];
    float* wt   = vsm;            // [2][16][68]
    float* ps   = vsm + 2176;     // [2][64][72]
    float* dwv  = vsm + 11392;    // [2][16]
    float* part = vsm + 11424;    // [128]

    int p  = blockIdx.x;
    int ii = p / 29;
    int jj = p - ii * 29;
    int base_pix = (ii * 4) * DIMS + jj * 4;

    int t = threadIdx.x;
    int lane = t & 31, wid = t >> 5;
    int g = lane >> 2;
    int q = lane & 3;

    if (t < 32)
        dwv[t] = dw[(t >> 4) * FLATN + (t & 15) * V4PIX + p];

    auto stage_w = [&](int s, int buf) {
        if (t < 64) {
            int o = t >> 2, c4 = t & 3;
            const float* src = vw + (((o << 3) + s) * V4PIX + p) * 64 + c4 * 16;
            float* dst = &wt[buf * 1088 + o * 68 + c4 * 16];
#pragma unroll
            for (int j = 0; j < 4; j++)
                cp_async16(dst + j * 4, src + j * 4);
        }
    };
    auto stage_p = [&](int s, int buf) {
#pragma unroll
        for (int f0 = 0; f0 < 8; f0++) {
            int f = t + f0 * 128;
            int pos = f >> 4, bq = f & 15;
            int di = pos >> 3, dj = pos & 7;
            const float* src = g_cplx + (size_t)s * (NPIX * B64)
                             + (base_pix + di * DIMS + dj) * B64 + bq * 4;
            cp_async16(&ps[buf * 4608 + pos * 72 + bq * 4], src);
        }
    };

    float d[2][4];
#pragma unroll
    for (int n = 0; n < 2; n++)
#pragma unroll
        for (int r = 0; r < 4; r++) d[n][r] = 0.f;

    stage_w(0, 0);
    stage_p(0, 0);
    cp_commit();

    for (int s = 0; s < 8; s++) {
        int buf = s & 1;
        if (s < 7) {
            stage_w(s + 1, buf ^ 1);
            stage_p(s + 1, buf ^ 1);
            cp_commit();
            asm volatile("cp.async.wait_group 1;");
        } else {
            asm volatile("cp.async.wait_group 0;");
        }
        __syncthreads();

        const float* wb = &wt[buf * 1088];
        const float* pb = &ps[buf * 4608];

#pragma unroll
        for (int kt = 0; kt < 8; kt++) {
            int k0 = kt * 8;
            uint32_t a0 = to_tf32(wb[g * 68 + k0 + q]);
            uint32_t a1 = to_tf32(wb[(g + 8) * 68 + k0 + q]);
            uint32_t a2 = to_tf32(wb[g * 68 + k0 + q + 4]);
            uint32_t a3 = to_tf32(wb[(g + 8) * 68 + k0 + q + 4]);
#pragma unroll
            for (int nl = 0; nl < 2; nl++) {
                int nt = 2 * wid + nl;
                uint32_t b0 = to_tf32(pb[(k0 + q) * 72 + 8 * nt + g]);
                uint32_t b1 = to_tf32(pb[(k0 + q + 4) * 72 + 8 * nt + g]);
                asm volatile(
                    "mma.sync.aligned.m16n8k8.row.col.f32.tf32.tf32.f32 "
                    "{%0,%1,%2,%3}, {%4,%5,%6,%7}, {%8,%9}, {%0,%1,%2,%3};"
                    : "+f"(d[nl][0]), "+f"(d[nl][1]), "+f"(d[nl][2]), "+f"(d[nl][3])
                    : "r"(a0), "r"(a1), "r"(a2), "r"(a3), "r"(b0), "r"(b1));
            }
        }
        __syncthreads();
    }

    float dw0g = dwv[g],      dw0h = dwv[g + 8];
    float dw1g = dwv[16 + g], dw1h = dwv[16 + g + 8];
#pragma unroll
    for (int nl = 0; nl < 2; nl++) {
        int nt = 2 * wid + nl;
        float c00 = d[nl][0] * dw0g + d[nl][2] * dw0h;
        float c01 = d[nl][1] * dw0g + d[nl][3] * dw0h;
        float c10 = d[nl][0] * dw1g + d[nl][2] * dw1h;
        float c11 = d[nl][1] * dw1g + d[nl][3] * dw1h;
#pragma unroll
        for (int m = 4; m < 32; m <<= 1) {
            c00 += __shfl_xor_sync(0xFFFFFFFFu, c00, m);
            c01 += __shfl_xor_sync(0xFFFFFFFFu, c01, m);
            c10 += __shfl_xor_sync(0xFFFFFFFFu, c10, m);
            c11 += __shfl_xor_sync(0xFFFFFFFFu, c11, m);
        }
        if (g == 0) {
            int b = 8 * nt + 2 * q;
            part[b * 2 + 0]       = c00;
            part[(b + 1) * 2 + 0] = c01;
            part[b * 2 + 1]       = c10;
            part[(b + 1) * 2 + 1] = c11;
        }
    }
    __syncthreads();
    g_part[p * 128 + t] = part[t];
}
#define V4_SMEM (11552 * 4)

// ---------------------------------------------------------------------------
// dec2: parallel deterministic reduction. Block t (0..127) owns output
// element t; 256 threads sum p-strided then fixed-order tree.
// ---------------------------------------------------------------------------
__global__ __launch_bounds__(256)
void dec2_kernel(const float* __restrict__ db, float* __restrict__ out)
{
    int t = blockIdx.x;          // output index b*2+cls
    int j = threadIdx.x;

    float ssum = 0.f;
    for (int p = j; p < V4PIX; p += 256)
        ssum += g_part[p * 128 + t];

    __shared__ float red[256];
    red[j] = ssum;
    __syncthreads();
    for (int off = 128; off > 0; off >>= 1) {
        if (j < off) red[j] += red[j + off];
        __syncthreads();
    }
    if (j == 0) out[t] = red[0] + db[t & 1];
}

// ---------------------------------------------------------------------------
extern "C" void kernel_launch(void* const* d_in, const int* in_sizes, int n_in,
                              void* d_out, int out_size)
{
    const float* x  = (const float*)d_in[0];   // [64,1,128,128]
    const float* sw = (const float*)d_in[1];   // [32,120,120,81]
    const float* vw = (const float*)d_in[2];   // [16,8,29,29,64]
    const float* dw = (const float*)d_in[3];   // [2,13456]
    const float* db = (const float*)d_in[4];   // [2]
    float* out = (float*)d_out;                // [64,2]

    cudaFuncSetAttribute(v1_kernel, cudaFuncAttributeMaxDynamicSharedMemorySize, V1_SMEM);
    cudaFuncSetAttribute(v4_kernel, cudaFuncAttributeMaxDynamicSharedMemorySize, V4_SMEM);

    v1_kernel<<<NPIX / PPB, 128, V1_SMEM>>>(x, sw);
    v4_kernel<<<V4PIX, 128, V4_SMEM>>>(vw, dw);
    dec2_kernel<<<128, 256>>>(db, out);
}